// round 16
// baseline (speedup 1.0000x reference)
#include <cuda_runtime.h>
#include <cuda_bf16.h>
#include <cuda_fp16.h>
#include <cstdint>

#define S     2048
#define HID   2048
#define NH    32
#define NKV   8
#define HD    64
#define KVDIM (NKV*HD)   // 512
#define CTX   (S-10)     // 2038: rows >= CTX use narrow rope

typedef unsigned long long ull;
typedef __nv_bfloat16 bf16;

__device__ __forceinline__ uint32_t smem_u32(const void* p) {
    uint32_t a;
    asm("{ .reg .u64 t; cvta.to.shared.u64 t, %1; cvt.u32.u64 %0, t; }" : "=r"(a) : "l"(p));
    return a;
}

// ---------------- mma.sync primitives (compute_103-safe) ----------------
__device__ __forceinline__ void cp16(uint32_t s, const void* g) {
    asm volatile("cp.async.cg.shared.global [%0], [%1], 16;" :: "r"(s), "l"(g));
}
#define CP_COMMIT() asm volatile("cp.async.commit_group;" ::: "memory")
#define CP_WAIT1()  asm volatile("cp.async.wait_group 1;" ::: "memory")

__device__ __forceinline__ void ldsm_x4(uint32_t addr, uint32_t& r0, uint32_t& r1,
                                        uint32_t& r2, uint32_t& r3) {
    asm volatile("ldmatrix.sync.aligned.m8n8.x4.shared.b16 {%0,%1,%2,%3}, [%4];"
                 : "=r"(r0), "=r"(r1), "=r"(r2), "=r"(r3) : "r"(addr));
}
__device__ __forceinline__ void ldsm_x4t(uint32_t addr, uint32_t& r0, uint32_t& r1,
                                         uint32_t& r2, uint32_t& r3) {
    asm volatile("ldmatrix.sync.aligned.m8n8.x4.trans.shared.b16 {%0,%1,%2,%3}, [%4];"
                 : "=r"(r0), "=r"(r1), "=r"(r2), "=r"(r3) : "r"(addr));
}
__device__ __forceinline__ void mma16816(float* c, const uint32_t* a, const uint32_t* b) {
    asm volatile(
        "mma.sync.aligned.m16n8k16.row.col.f32.bf16.bf16.f32 "
        "{%0,%1,%2,%3}, {%4,%5,%6,%7}, {%8,%9}, {%0,%1,%2,%3};"
        : "+f"(c[0]), "+f"(c[1]), "+f"(c[2]), "+f"(c[3])
        : "r"(a[0]), "r"(a[1]), "r"(a[2]), "r"(a[3]), "r"(b[0]), "r"(b[1]));
}
__device__ __forceinline__ void mma16816h(float* c, const uint32_t* a, const uint32_t* b) {
    asm volatile(
        "mma.sync.aligned.m16n8k16.row.col.f32.f16.f16.f32 "
        "{%0,%1,%2,%3}, {%4,%5,%6,%7}, {%8,%9}, {%0,%1,%2,%3};"
        : "+f"(c[0]), "+f"(c[1]), "+f"(c[2]), "+f"(c[3])
        : "r"(a[0]), "r"(a[1]), "r"(a[2]), "r"(a[3]), "r"(b[0]), "r"(b[1]));
}
__device__ __forceinline__ uint32_t pack_f16x2(float lo, float hi) {
    uint32_t r; asm("cvt.rn.f16x2.f32 %0, %1, %2;" : "=r"(r) : "f"(hi), "f"(lo));
    return r;
}

// ---------------- scratch (static device globals; no allocs) ----------------
__device__ __half g_hHf[S*HID],   g_hLf[S*HID];    // hidden fp16 hi/lo
__device__ __half g_WqF[HID*HID];
__device__ __half g_WkF[KVDIM*HID];
__device__ __half g_WvF[KVDIM*HID];
__device__ __half g_WoF[HID*HID];
__device__ __half g_aHf[S*HID],  g_aLf[S*HID];     // attn out fp16 hi/lo
__device__ bf16 g_Qh[S*HID],    g_Ql[S*HID];
__device__ bf16 g_bKh[S*KVDIM], g_bKl[S*KVDIM];
__device__ bf16 g_nKh[S*KVDIM], g_nKl[S*KVDIM];
__device__ __half g_Vh[S*KVDIM], g_Vl[S*KVDIM];
__device__ float4 g_trig[S*32];                    // {cos_b, sin_b, cos_n, sin_n}
// dual split-K partials
#define DSPLIT 4
#define DTILES (32/DSPLIT)
__device__ float g_pO[DSPLIT*NH*64*64];
__device__ float g_pm[DSPLIT*NH*64];
__device__ float g_pl[DSPLIT*NH*64];

// ---------------- trig table ------------------------------------------------
__global__ __launch_bounds__(256)
void trig_kernel(float4* __restrict__ tab)
{
    int idx = blockIdx.x * 256 + threadIdx.x;   // 65536
    int s = idx >> 5, d = idx & 31;
    double inv = pow(10000.0, -(double)d / 32.0);
    double ab = (double)s * inv;
    double an = ((double)s * 0.25) * inv;
    tab[idx] = make_float4((float)cos(ab), (float)sin(ab),
                           (float)cos(an), (float)sin(an));
}

// ---------------- input conversions (one launch) ----------------------------
__global__ __launch_bounds__(256)
void split_all_kernel(const float* __restrict__ hid, const float* __restrict__ Wq,
                      const float* __restrict__ Wk,  const float* __restrict__ Wv,
                      const float* __restrict__ Wo,
                      __half* __restrict__ hH, __half* __restrict__ hL,
                      __half* __restrict__ qF, __half* __restrict__ kF,
                      __half* __restrict__ vF, __half* __restrict__ oF)
{
    int g0 = (blockIdx.x * 256 + threadIdx.x) * 4;
    const int R0 = 1048576, R1 = R0 + 1048576, R2 = R1 + 262144, R3 = R2 + 262144;
    const int TOT = R3 + 1048576;
    if (g0 >= TOT) return;
    if (g0 < R0) {
#pragma unroll
        for (int k = 0; k < 4; k++) {
            int i = g0 + k;
            float4 v = ((const float4*)hid)[i];
            __half h0 = __float2half_rn(v.x), h1 = __float2half_rn(v.y);
            __half h2 = __float2half_rn(v.z), h3 = __float2half_rn(v.w);
            ((__half2*)hH)[i*2+0] = __half2(h0, h1);
            ((__half2*)hH)[i*2+1] = __half2(h2, h3);
            ((__half2*)hL)[i*2+0] = __half2(__float2half_rn(v.x - __half2float(h0)),
                                            __float2half_rn(v.y - __half2float(h1)));
            ((__half2*)hL)[i*2+1] = __half2(__float2half_rn(v.z - __half2float(h2)),
                                            __float2half_rn(v.w - __half2float(h3)));
        }
        return;
    }
    const float* src; __half* dst; int rb;
    if (g0 < R1)      { src = Wq; dst = qF; rb = R0; }
    else if (g0 < R2) { src = Wk; dst = kF; rb = R1; }
    else if (g0 < R3) { src = Wv; dst = vF; rb = R2; }
    else              { src = Wo; dst = oF; rb = R3; }
#pragma unroll
    for (int k = 0; k < 4; k++) {
        int i = g0 - rb + k;
        float4 v = ((const float4*)src)[i];
        ((__half2*)dst)[i*2+0] = __half2(__float2half_rn(v.x), __float2half_rn(v.y));
        ((__half2*)dst)[i*2+1] = __half2(__float2half_rn(v.z), __float2half_rn(v.w));
    }
}

// ---------------- 2-pass fp16 GEMM mainloop: acc = (Ah+Al) @ Bh^T -----------
#define STG2      16384
#define SM_STAGE2 (3*STG2)        // 48 KB
#define SM_TOTAL2 (2*SM_STAGE2)   // 96 KB -> 2 CTAs/SM

__device__ __forceinline__ void g_load_stage2(
    uint32_t sbuf,
    const __half* __restrict__ Ah, const __half* __restrict__ Al,
    const __half* __restrict__ Bh,
    int mBase, int nBase, int Kdim, int k0, int tid)
{
#pragma unroll
    for (int i = 0; i < 4; i++) {
        int u = i * 256 + tid;
        int r = u >> 3, c = u & 7;
        uint32_t so = (uint32_t)(r * 128 + ((c ^ (r & 7)) << 4));
        size_t eoffA = (size_t)(mBase + r) * Kdim + k0 + c * 8;
        size_t eoffB = (size_t)(nBase + r) * Kdim + k0 + c * 8;
        cp16(sbuf +          so, Ah + eoffA);
        cp16(sbuf +   STG2 + so, Al + eoffA);
        cp16(sbuf + 2*STG2 + so, Bh + eoffB);
    }
}

__device__ __forceinline__ void gemm2_mainloop(
    const __half* __restrict__ Ah, const __half* __restrict__ Al,
    const __half* __restrict__ Bh,
    int Kdim, int mBase, int nBase, uint32_t sb, float acc[4][4][4])
{
    const int tid  = threadIdx.x;
    const int lane = tid & 31;
    const int wid  = tid >> 5;
    const int wm   = wid & 1;
    const int wn   = wid >> 1;

#pragma unroll
    for (int i = 0; i < 4; i++)
#pragma unroll
        for (int j = 0; j < 4; j++)
#pragma unroll
            for (int k = 0; k < 4; k++) acc[i][j][k] = 0.0f;

    const int NC = Kdim >> 6;

    g_load_stage2(sb,             Ah, Al, Bh, mBase, nBase, Kdim, 0,  tid);
    CP_COMMIT();
    g_load_stage2(sb + SM_STAGE2, Ah, Al, Bh, mBase, nBase, Kdim, 64, tid);
    CP_COMMIT();

    const int aRow = wm * 64;
    const int bRow = wn * 32;

    for (int c = 0; c < NC; c++) {
        CP_WAIT1();
        __syncthreads();
        const uint32_t sbuf = sb + (c & 1) * SM_STAGE2;
        const uint32_t sAh = sbuf, sAl = sbuf + STG2, sBh = sbuf + 2*STG2;

#pragma unroll
        for (int ks = 0; ks < 4; ks++) {
            uint32_t aH[4][4], aL[4][4], bH[4][2];
            {
                int rA = aRow + (lane & 15);
                int ccA = ks * 2 + (lane >> 4);
#pragma unroll
                for (int mf = 0; mf < 4; mf++) {
                    int r = rA + mf * 16;
                    uint32_t so = (uint32_t)(r * 128 + ((ccA ^ (r & 7)) << 4));
                    ldsm_x4(sAh + so, aH[mf][0], aH[mf][1], aH[mf][2], aH[mf][3]);
                    ldsm_x4(sAl + so, aL[mf][0], aL[mf][1], aL[mf][2], aL[mf][3]);
                }
            }
            {
                int rB0 = bRow + (lane & 7) + ((lane >> 4) << 3);
                int ccB = ks * 2 + ((lane >> 3) & 1);
#pragma unroll
                for (int nf2 = 0; nf2 < 2; nf2++) {
                    int r = rB0 + nf2 * 16;
                    uint32_t so = (uint32_t)(r * 128 + ((ccB ^ (r & 7)) << 4));
                    ldsm_x4(sBh + so, bH[nf2*2][0], bH[nf2*2][1], bH[nf2*2+1][0], bH[nf2*2+1][1]);
                }
            }
#pragma unroll
            for (int mf = 0; mf < 4; mf++)
#pragma unroll
                for (int nf = 0; nf < 4; nf++) {
                    mma16816h(acc[mf][nf], aH[mf], bH[nf]);
                    mma16816h(acc[mf][nf], aL[mf], bH[nf]);
                }
        }
        __syncthreads();
        if (c + 2 < NC)
            g_load_stage2(sb + (c & 1) * SM_STAGE2, Ah, Al, Bh,
                          mBase, nBase, Kdim, (c + 2) * 64, tid);
        CP_COMMIT();
    }
}

// Wo GEMM: fp32 store epilogue (into d_out)
__global__ __launch_bounds__(256, 2)
void wo_gemm2(const __half* __restrict__ Ah, const __half* __restrict__ Al,
              const __half* __restrict__ Bh, float* __restrict__ C)
{
    extern __shared__ char dyns[];
    uint32_t sb = smem_u32(dyns);
    const int mBase = blockIdx.y * 128, nBase = blockIdx.x * 128;
    float acc[4][4][4];
    gemm2_mainloop(Ah, Al, Bh, HID, mBase, nBase, sb, acc);

    const int lane = threadIdx.x & 31, wid = threadIdx.x >> 5;
    const int wm = wid & 1, wn = wid >> 1;
#pragma unroll
    for (int mf = 0; mf < 4; mf++) {
        int row0 = mBase + wm * 64 + mf * 16 + (lane >> 2);
#pragma unroll
        for (int nf = 0; nf < 4; nf++) {
            int col = nBase + wn * 32 + nf * 8 + (lane & 3) * 2;
            *(float2*)&C[(size_t)row0 * HID + col]       = make_float2(acc[mf][nf][0], acc[mf][nf][1]);
            *(float2*)&C[(size_t)(row0 + 8) * HID + col] = make_float2(acc[mf][nf][2], acc[mf][nf][3]);
        }
    }
}

// helper: bf16 hi/lo pair store
__device__ __forceinline__ void split_w2(bf16* hp, bf16* lp, float x0, float x1) {
    bf16 h0 = __float2bfloat16(x0);
    bf16 h1 = __float2bfloat16(x1);
    *(__nv_bfloat162*)hp = __nv_bfloat162(h0, h1);
    *(__nv_bfloat162*)lp = __nv_bfloat162(__float2bfloat16(x0 - __bfloat162float(h0)),
                                          __float2bfloat16(x1 - __bfloat162float(h1)));
}

// fused QKV projection + rope + splits.
// bx 0..15 -> Q (rope per-row variant, scale, bf16 h/l)
// bx 16..19 -> K (both rope variants, bf16 h/l x2)
// bx 20..23 -> V (fp16 h/l, no rope)
#define SPAD 132
__global__ __launch_bounds__(256, 2)
void qkv_gemm2(const __half* __restrict__ Ah, const __half* __restrict__ Al,
               const __half* __restrict__ WqF, const __half* __restrict__ WkF,
               const __half* __restrict__ WvF,
               const float4* __restrict__ trig,
               bf16* __restrict__ qh, bf16* __restrict__ ql,
               bf16* __restrict__ kbh, bf16* __restrict__ kbl,
               bf16* __restrict__ knh, bf16* __restrict__ knl,
               __half* __restrict__ vh, __half* __restrict__ vl)
{
    extern __shared__ char dyns[];
    uint32_t sb = smem_u32(dyns);
    const int bx = blockIdx.x, mBase = blockIdx.y * 128;
    const int tid = threadIdx.x, lane = tid & 31, wid = tid >> 5;
    const int wm = wid & 1, wn = wid >> 1;
    const float QS = 1.4426950408889634f * 0.125f;   // log2(e)/sqrt(64)

    float acc[4][4][4];

    if (bx >= 20) {
        // ---- V: plain GEMM + fp16 hi/lo split from registers ----
        const int nBase = (bx - 20) * 128;
        gemm2_mainloop(Ah, Al, WvF, HID, mBase, nBase, sb, acc);
#pragma unroll
        for (int mf = 0; mf < 4; mf++) {
            int row0 = mBase + wm * 64 + mf * 16 + (lane >> 2);
#pragma unroll
            for (int nf = 0; nf < 4; nf++) {
                int col = nBase + wn * 32 + nf * 8 + (lane & 3) * 2;
#pragma unroll
                for (int half = 0; half < 2; half++) {
                    int r = row0 + half * 8;
                    float x0 = acc[mf][nf][half*2+0], x1 = acc[mf][nf][half*2+1];
                    float r0 = __half2float(__float2half_rn(x0));
                    float r1 = __half2float(__float2half_rn(x1));
                    *(uint32_t*)&vh[(size_t)r * KVDIM + col] = pack_f16x2(x0, x1);
                    *(uint32_t*)&vl[(size_t)r * KVDIM + col] = pack_f16x2(x0 - r0, x1 - r1);
                }
            }
        }
        return;
    }

    const bool isQ = (bx < 16);
    const int nBase = isQ ? bx * 128 : (bx - 16) * 128;
    gemm2_mainloop(Ah, Al, isQ ? WqF : WkF, HID, mBase, nBase, sb, acc);

    // ---- stage fp32 tile to smem (padded rows), then rope+split ----
    float* stage = (float*)dyns;          // 128 x SPAD floats = 67.5 KB
#pragma unroll
    for (int mf = 0; mf < 4; mf++) {
        int rl0 = wm * 64 + mf * 16 + (lane >> 2);
#pragma unroll
        for (int nf = 0; nf < 4; nf++) {
            int cl = wn * 32 + nf * 8 + (lane & 3) * 2;
            stage[rl0 * SPAD + cl]       = acc[mf][nf][0];
            stage[rl0 * SPAD + cl + 1]   = acc[mf][nf][1];
            stage[(rl0+8) * SPAD + cl]   = acc[mf][nf][2];
            stage[(rl0+8) * SPAD + cl+1] = acc[mf][nf][3];
        }
    }
    __syncthreads();

    const int r = tid >> 1;               // local row 0..127
    const int half = tid & 1;             // which head (64-col) in the 128-col tile
    const int grow = mBase + r;
    const float* srow = stage + r * SPAD + half * 64;
    const float4* tb = trig + (size_t)grow * 32;

    if (isQ) {
        const bool narrow = (grow >= CTX);
        size_t base = (size_t)grow * HID + nBase + half * 64;
#pragma unroll
        for (int d = 0; d < 32; d += 2) {
            float4 t0 = tb[d], t1 = tb[d+1];
            float c0 = narrow ? t0.z : t0.x, s0 = narrow ? t0.w : t0.y;
            float c1 = narrow ? t1.z : t1.x, s1 = narrow ? t1.w : t1.y;
            float x1a = srow[d],    x1b = srow[d+1];
            float x2a = srow[d+32], x2b = srow[d+33];
            split_w2(qh + base + d,      ql + base + d,
                     (x1a*c0 - x2a*s0)*QS, (x1b*c1 - x2b*s1)*QS);
            split_w2(qh + base + d + 32, ql + base + d + 32,
                     (x2a*c0 + x1a*s0)*QS, (x2b*c1 + x1b*s1)*QS);
        }
    } else {
        size_t base = (size_t)grow * KVDIM + nBase + half * 64;
#pragma unroll
        for (int d = 0; d < 32; d += 2) {
            float4 t0 = tb[d], t1 = tb[d+1];
            float x1a = srow[d],    x1b = srow[d+1];
            float x2a = srow[d+32], x2b = srow[d+33];
            split_w2(kbh + base + d,      kbl + base + d,
                     x1a*t0.x - x2a*t0.y, x1b*t1.x - x2b*t1.y);
            split_w2(kbh + base + d + 32, kbl + base + d + 32,
                     x2a*t0.x + x1a*t0.y, x2b*t1.x + x1b*t1.y);
            split_w2(knh + base + d,      knl + base + d,
                     x1a*t0.z - x2a*t0.w, x1b*t1.z - x2b*t1.w);
            split_w2(knh + base + d + 32, knl + base + d + 32,
                     x2a*t0.z + x1a*t0.w, x2b*t1.z + x1b*t1.w);
        }
    }
}

// ---------------- Tensor-core flash attention (unchanged from R15) ---------
template<bool DUAL>
__device__ __forceinline__ void fa_load_stage(
    uint32_t sb, int kt, int kvh, int tid,
    const bf16* __restrict__ Kbh, const bf16* __restrict__ Kbl,
    const bf16* __restrict__ Knh, const bf16* __restrict__ Knl,
    const __half* __restrict__ Vh, const __half* __restrict__ Vl)
{
#pragma unroll
    for (int i = 0; i < 4; i++) {
        int u = i * 128 + tid;
        int r = u >> 3, c = u & 7;
        uint32_t so = (uint32_t)(r * 128 + ((c ^ (r & 7)) << 4));
        size_t go = (size_t)(kt * 64 + r) * KVDIM + kvh * 64 + c * 8;
        cp16(sb +         so, Kbh + go);
        cp16(sb + 8192  + so, Kbl + go);
        cp16(sb + 16384 + so, Vh + go);
        cp16(sb + 24576 + so, Vl + go);
        if (DUAL) {
            cp16(sb + 32768 + so, Knh + go);
            cp16(sb + 40960 + so, Knl + go);
        }
    }
}

__device__ __forceinline__ void fa_compute_S(
    float s[8][4], uint32_t sKh, uint32_t sKl,
    const uint32_t qfh[4][4], const uint32_t qfl[4][4], int lane)
{
#pragma unroll
    for (int kk = 0; kk < 4; kk++) {
        uint32_t kh[8][2], kl[8][2];
        int rB0 = (lane & 7) + ((lane >> 4) << 3);
        int ccB = kk * 2 + ((lane >> 3) & 1);
#pragma unroll
        for (int nb = 0; nb < 4; nb++) {
            int r = nb * 16 + rB0;
            uint32_t so = (uint32_t)(r * 128 + ((ccB ^ (r & 7)) << 4));
            ldsm_x4(sKh + so, kh[nb*2][0], kh[nb*2][1], kh[nb*2+1][0], kh[nb*2+1][1]);
            ldsm_x4(sKl + so, kl[nb*2][0], kl[nb*2][1], kl[nb*2+1][0], kl[nb*2+1][1]);
        }
#pragma unroll
        for (int nf = 0; nf < 8; nf++) {
            mma16816(s[nf], qfh[kk], kh[nf]);
            mma16816(s[nf], qfl[kk], kh[nf]);
            mma16816(s[nf], qfh[kk], kl[nf]);
        }
    }
}

__device__ __forceinline__ void fa_load_qfrag(
    uint32_t sQ, const bf16* __restrict__ Qh, const bf16* __restrict__ Ql,
    int qt, int h, int tid)
{
    const bf16* gQh = Qh + (size_t)(qt * 64) * HID + h * 64;
    const bf16* gQl = Ql + (size_t)(qt * 64) * HID + h * 64;
#pragma unroll
    for (int i = 0; i < 4; i++) {
        int u = i * 128 + tid;
        int r = u >> 3, c = u & 7;
        uint32_t so = (uint32_t)(r * 128 + ((c ^ (r & 7)) << 4));
        cp16(sQ +        so, gQh + (size_t)r * HID + c * 8);
        cp16(sQ + 8192 + so, gQl + (size_t)r * HID + c * 8);
    }
}

struct FaState {
    float o[8][4];
    float m0, m1, l0, l1;
};

__device__ __forceinline__ void fa_softmax_pv(
    FaState& st, float s[8][4], uint32_t sb, int lane)
{
    float mr0 = -1e30f, mr1 = -1e30f;
#pragma unroll
    for (int nf = 0; nf < 8; nf++) {
        mr0 = fmaxf(mr0, fmaxf(s[nf][0], s[nf][1]));
        mr1 = fmaxf(mr1, fmaxf(s[nf][2], s[nf][3]));
    }
    mr0 = fmaxf(mr0, __shfl_xor_sync(0xffffffffu, mr0, 1));
    mr0 = fmaxf(mr0, __shfl_xor_sync(0xffffffffu, mr0, 2));
    mr1 = fmaxf(mr1, __shfl_xor_sync(0xffffffffu, mr1, 1));
    mr1 = fmaxf(mr1, __shfl_xor_sync(0xffffffffu, mr1, 2));

    float mn0 = fmaxf(st.m0, mr0), mn1 = fmaxf(st.m1, mr1);
    float sc0 = exp2f(st.m0 - mn0), sc1 = exp2f(st.m1 - mn1);
    st.m0 = mn0; st.m1 = mn1;
    st.l0 *= sc0; st.l1 *= sc1;
#pragma unroll
    for (int nf = 0; nf < 8; nf++) {
        st.o[nf][0] *= sc0; st.o[nf][1] *= sc0;
        st.o[nf][2] *= sc1; st.o[nf][3] *= sc1;
    }

    uint32_t pF[4][4];
    float sum0 = 0.0f, sum1 = 0.0f;
#pragma unroll
    for (int nf = 0; nf < 8; nf++) {
        float p0 = exp2f(s[nf][0] - st.m0), p1 = exp2f(s[nf][1] - st.m0);
        float p2 = exp2f(s[nf][2] - st.m1), p3 = exp2f(s[nf][3] - st.m1);
        sum0 += p0 + p1; sum1 += p2 + p3;
        int kk = nf >> 1;
        int off = (nf & 1) * 2;
        pF[kk][off + 0] = pack_f16x2(p0, p1);
        pF[kk][off + 1] = pack_f16x2(p2, p3);
    }
    sum0 += __shfl_xor_sync(0xffffffffu, sum0, 1);
    sum0 += __shfl_xor_sync(0xffffffffu, sum0, 2);
    sum1 += __shfl_xor_sync(0xffffffffu, sum1, 1);
    sum1 += __shfl_xor_sync(0xffffffffu, sum1, 2);
    st.l0 += sum0; st.l1 += sum1;

    const uint32_t sVh = sb + 16384, sVl = sb + 24576;
#pragma unroll
    for (int kk = 0; kk < 4; kk++) {
        uint32_t vh[8][2], vl[8][2];
        int key0 = kk * 16 + (lane & 7) + ((lane >> 3) & 1) * 8;
#pragma unroll
        for (int nb = 0; nb < 4; nb++) {
            int chunk = nb * 2 + (lane >> 4);
            uint32_t so = (uint32_t)(key0 * 128 + ((chunk ^ (key0 & 7)) << 4));
            ldsm_x4t(sVh + so, vh[nb*2][0], vh[nb*2][1], vh[nb*2+1][0], vh[nb*2+1][1]);
            ldsm_x4t(sVl + so, vl[nb*2][0], vl[nb*2][1], vl[nb*2+1][0], vl[nb*2+1][1]);
        }
#pragma unroll
        for (int nf = 0; nf < 8; nf++) {
            mma16816h(st.o[nf], pF[kk], vh[nf]);
            mma16816h(st.o[nf], pF[kk], vl[nf]);
        }
    }
}

__global__ __launch_bounds__(128, 2)
void flash_all(const bf16* __restrict__ Qh, const bf16* __restrict__ Ql,
               const bf16* __restrict__ Kbh, const bf16* __restrict__ Kbl,
               const bf16* __restrict__ Knh, const bf16* __restrict__ Knl,
               const __half* __restrict__ Vh,  const __half* __restrict__ Vl,
               __half* __restrict__ aHf, __half* __restrict__ aLf,
               float* __restrict__ pO, float* __restrict__ pm,
               float* __restrict__ pl)
{
    extern __shared__ char dyn[];
    const uint32_t sQ = smem_u32(dyn);
    const int tid = threadIdx.x, lane = tid & 31, w = tid >> 5;
    const int h = blockIdx.y, kvh = h >> 2;
    const bool isDual = (blockIdx.x < DSPLIT);

    FaState st;
#pragma unroll
    for (int nf = 0; nf < 8; nf++)
#pragma unroll
        for (int j = 0; j < 4; j++) st.o[nf][j] = 0.0f;
    st.m0 = -1e30f; st.m1 = -1e30f; st.l0 = 0.0f; st.l1 = 0.0f;

    if (isDual) {
        constexpr int STAGE = 49152;
        const int split = blockIdx.x;
        const int qt = S/64 - 1;
        const int kt0 = split * DTILES, kt1 = kt0 + DTILES;

        fa_load_qfrag(sQ, Qh, Ql, qt, h, tid);
        fa_load_stage<true>(sQ + 16384, kt0, kvh, tid, Kbh, Kbl, Knh, Knl, Vh, Vl);
        CP_COMMIT();
        fa_load_stage<true>(sQ + 16384 + STAGE, kt0 + 1, kvh, tid, Kbh, Kbl, Knh, Knl, Vh, Vl);
        CP_COMMIT();
        CP_WAIT1();
        __syncthreads();

        uint32_t qfh[4][4], qfl[4][4];
        {
            int rA = w * 16 + (lane & 15);
#pragma unroll
            for (int kk = 0; kk < 4; kk++) {
                int cc = kk * 2 + (lane >> 4);
                uint32_t so = (uint32_t)(rA * 128 + ((cc ^ (rA & 7)) << 4));
                ldsm_x4(sQ + so,        qfh[kk][0], qfh[kk][1], qfh[kk][2], qfh[kk][3]);
                ldsm_x4(sQ + 8192 + so, qfl[kk][0], qfl[kk][1], qfl[kk][2], qfl[kk][3]);
            }
        }

        const int rl0 = w * 16 + (lane >> 2);
        const int rl1 = rl0 + 8;
        const int rg0 = qt * 64 + rl0, rg1 = qt * 64 + rl1;

        for (int kt = kt0; kt < kt1; kt++) {
            if (kt > kt0) { CP_WAIT1(); __syncthreads(); }
            const uint32_t sb = sQ + 16384 + (kt & 1) * STAGE;

            float s[8][4];
#pragma unroll
            for (int nf = 0; nf < 8; nf++)
#pragma unroll
                for (int j = 0; j < 4; j++) s[nf][j] = 0.0f;
            fa_compute_S(s, sb, sb + 8192, qfh, qfl, lane);

            {
                float sn[8][4];
#pragma unroll
                for (int nf = 0; nf < 8; nf++)
#pragma unroll
                    for (int j = 0; j < 4; j++) sn[nf][j] = 0.0f;
                fa_compute_S(sn, sb + 32768, sb + 40960, qfh, qfl, lane);
                if (rg0 >= CTX) {
#pragma unroll
                    for (int nf = 0; nf < 8; nf++) { s[nf][0] = sn[nf][0]; s[nf][1] = sn[nf][1]; }
                }
                if (rg1 >= CTX) {
#pragma unroll
                    for (int nf = 0; nf < 8; nf++) { s[nf][2] = sn[nf][2]; s[nf][3] = sn[nf][3]; }
                }
            }

            if (kt == qt) {
#pragma unroll
                for (int nf = 0; nf < 8; nf++) {
                    int c0 = kt * 64 + nf * 8 + (lane & 3) * 2;
                    if (c0     > rg0) s[nf][0] = -1e30f;
                    if (c0 + 1 > rg0) s[nf][1] = -1e30f;
                    if (c0     > rg1) s[nf][2] = -1e30f;
                    if (c0 + 1 > rg1) s[nf][3] = -1e30f;
                }
            }

            fa_softmax_pv(st, s, sb, lane);

            __syncthreads();
            if (kt + 2 < kt1)
                fa_load_stage<true>(sQ + 16384 + (kt & 1) * STAGE, kt + 2, kvh, tid,
                                    Kbh, Kbl, Knh, Knl, Vh, Vl);
            CP_COMMIT();
        }

        const int hb = (split * NH + h) * 64;
#pragma unroll
        for (int nf = 0; nf < 8; nf++) {
            int col = nf * 8 + (lane & 3) * 2;
            *(float2*)&pO[(size_t)(hb + rl0) * 64 + col] = make_float2(st.o[nf][0], st.o[nf][1]);
            *(float2*)&pO[(size_t)(hb + rl1) * 64 + col] = make_float2(st.o[nf][2], st.o[nf][3]);
        }
        if ((lane & 3) == 0) {
            pm[hb + rl0] = st.m0; pl[hb + rl0] = st.l0;
            pm[hb + rl1] = st.m1; pl[hb + rl1] = st.l1;
        }
        return;
    }

    {
        constexpr int STAGE = 32768;
        const int qt = (S/64 - 2) - ((int)blockIdx.x - DSPLIT);

        fa_load_qfrag(sQ, Qh, Ql, qt, h, tid);
        fa_load_stage<false>(sQ + 16384, 0, kvh, tid, Kbh, Kbl, nullptr, nullptr, Vh, Vl);
        CP_COMMIT();
        if (qt >= 1)
            fa_load_stage<false>(sQ + 16384 + STAGE, 1, kvh, tid, Kbh, Kbl, nullptr, nullptr, Vh, Vl);
        CP_COMMIT();
        CP_WAIT1();
        __syncthreads();

        uint32_t qfh[4][4], qfl[4][4];
        {
            int rA = w * 16 + (lane & 15);
#pragma unroll
            for (int kk = 0; kk < 4; kk++) {
                int cc = kk * 2 + (lane >> 4);
                uint32_t so = (uint32_t)(rA * 128 + ((cc ^ (rA & 7)) << 4));
                ldsm_x4(sQ + so,        qfh[kk][0], qfh[kk][1], qfh[kk][2], qfh[kk][3]);
                ldsm_x4(sQ + 8192 + so, qfl[kk][0], qfl[kk][1], qfl[kk][2], qfl[kk][3]);
            }
        }

        const int rg0 = qt * 64 + w * 16 + (lane >> 2);
        const int rg1 = rg0 + 8;

        for (int kt = 0; kt <= qt; kt++) {
            if (kt) { CP_WAIT1(); __syncthreads(); }
            const uint32_t sb = sQ + 16384 + (kt & 1) * STAGE;

            float s[8][4];
#pragma unroll
            for (int nf = 0; nf < 8; nf++)
#pragma unroll
                for (int j = 0; j < 4; j++) s[nf][j] = 0.0f;
            fa_compute_S(s, sb, sb + 8192, qfh, qfl, lane);

            if (kt == qt) {
#pragma unroll
                for (int nf = 0; nf < 8; nf++) {
                    int c0 = kt * 64 + nf * 8 + (lane & 3) * 2;
                    if (c0     > rg0) s[nf][0] = -1e30f;
                    if (c0 + 1 > rg0) s[nf][1] = -1e30f;
                    if (c0     > rg1) s[nf][2] = -1e30f;
                    if (c0 + 1 > rg1) s[nf][3] = -1e30f;
                }
            }

            fa_softmax_pv(st, s, sb, lane);

            __syncthreads();
            if (kt + 2 <= qt)
                fa_load_stage<false>(sQ + 16384 + (kt & 1) * STAGE, kt + 2, kvh, tid,
                                     Kbh, Kbl, nullptr, nullptr, Vh, Vl);
            CP_COMMIT();
        }

        float inv0 = 1.0f / st.l0, inv1 = 1.0f / st.l1;
#pragma unroll
        for (int nf = 0; nf < 8; nf++) {
            int col = h * 64 + nf * 8 + (lane & 3) * 2;
            float x0 = st.o[nf][0]*inv0, x1 = st.o[nf][1]*inv0;
            float x2 = st.o[nf][2]*inv1, x3 = st.o[nf][3]*inv1;
            float r0 = __half2float(__float2half_rn(x0));
            float r1 = __half2float(__float2half_rn(x1));
            float r2 = __half2float(__float2half_rn(x2));
            float r3 = __half2float(__float2half_rn(x3));
            *(uint32_t*)&aHf[(size_t)rg0 * HID + col] = pack_f16x2(x0, x1);
            *(uint32_t*)&aLf[(size_t)rg0 * HID + col] = pack_f16x2(x0 - r0, x1 - r1);
            *(uint32_t*)&aHf[(size_t)rg1 * HID + col] = pack_f16x2(x2, x3);
            *(uint32_t*)&aLf[(size_t)rg1 * HID + col] = pack_f16x2(x2 - r2, x3 - r3);
        }
    }
}

// ---- merge dual partials -> fp16 hi/lo attn output (exact reassociation) --
__global__ __launch_bounds__(256)
void dual_merge(const float* __restrict__ pO, const float* __restrict__ pm,
                const float* __restrict__ pl,
                __half* __restrict__ aHf, __half* __restrict__ aLf)
{
    int idx = blockIdx.x * 256 + threadIdx.x;
    if (idx >= 64 * NH * 32) return;
    int dp = idx & 31;
    int h  = (idx >> 5) & 31;
    int rl = idx >> 10;

    float m[DSPLIT], l[DSPLIT];
#pragma unroll
    for (int i = 0; i < DSPLIT; i++) {
        m[i] = pm[(i * NH + h) * 64 + rl];
        l[i] = pl[(i * NH + h) * 64 + rl];
    }
    float M = m[0];
#pragma unroll
    for (int i = 1; i < DSPLIT; i++) M = fmaxf(M, m[i]);
    float wgt[DSPLIT], L = 0.0f;
#pragma unroll
    for (int i = 0; i < DSPLIT; i++) { wgt[i] = exp2f(m[i] - M); L += l[i] * wgt[i]; }

    float o0 = 0.0f, o1 = 0.0f;
#pragma unroll
    for (int i = 0; i < DSPLIT; i++) {
        float2 v = *(const float2*)&pO[(size_t)((i * NH + h) * 64 + rl) * 64 + dp * 2];
        o0 += v.x * wgt[i];
        o1 += v.y * wgt[i];
    }
    float inv = 1.0f / L;
    o0 *= inv; o1 *= inv;

    size_t off = (size_t)((S - 64) + rl) * HID + h * 64 + dp * 2;
    float r0 = __half2float(__float2half_rn(o0));
    float r1 = __half2float(__float2half_rn(o1));
    *(uint32_t*)&aHf[off] = pack_f16x2(o0, o1);
    *(uint32_t*)&aLf[off] = pack_f16x2(o0 - r0, o1 - r1);
}

// ---------------- launch ----------------
extern "C" void kernel_launch(void* const* d_in, const int* in_sizes, int n_in,
                              void* d_out, int out_size)
{
    const float* hidden = (const float*)d_in[0];
    const float* Wq = (const float*)d_in[3];
    const float* Wk = (const float*)d_in[4];
    const float* Wv = (const float*)d_in[5];
    const float* Wo = (const float*)d_in[6];
    float* out = (float*)d_out;

    __half *hHf,*hLf,*WqF,*WkF,*WvF,*WoF,*aHf,*aLf;
    cudaGetSymbolAddress((void**)&hHf, g_hHf); cudaGetSymbolAddress((void**)&hLf, g_hLf);
    cudaGetSymbolAddress((void**)&WqF, g_WqF); cudaGetSymbolAddress((void**)&WkF, g_WkF);
    cudaGetSymbolAddress((void**)&WvF, g_WvF); cudaGetSymbolAddress((void**)&WoF, g_WoF);
    cudaGetSymbolAddress((void**)&aHf, g_aHf); cudaGetSymbolAddress((void**)&aLf, g_aLf);

    bf16 *Qh,*Ql,*bKh,*bKl,*nKh,*nKl;
    __half *Vh,*Vl;
    cudaGetSymbolAddress((void**)&Qh,  g_Qh);  cudaGetSymbolAddress((void**)&Ql,  g_Ql);
    cudaGetSymbolAddress((void**)&bKh, g_bKh); cudaGetSymbolAddress((void**)&bKl, g_bKl);
    cudaGetSymbolAddress((void**)&nKh, g_nKh); cudaGetSymbolAddress((void**)&nKl, g_nKl);
    cudaGetSymbolAddress((void**)&Vh,  g_Vh);  cudaGetSymbolAddress((void**)&Vl,  g_Vl);

    float4* trig;
    cudaGetSymbolAddress((void**)&trig, g_trig);

    float *pO, *pm, *pl;
    cudaGetSymbolAddress((void**)&pO, g_pO);
    cudaGetSymbolAddress((void**)&pm, g_pm);
    cudaGetSymbolAddress((void**)&pl, g_pl);

    cudaFuncSetAttribute(qkv_gemm2, cudaFuncAttributeMaxDynamicSharedMemorySize, SM_TOTAL2);
    cudaFuncSetAttribute(wo_gemm2,  cudaFuncAttributeMaxDynamicSharedMemorySize, SM_TOTAL2);
    const int FA_SMEM_D = 16384 + 2*49152;   // 114688
    cudaFuncSetAttribute(flash_all, cudaFuncAttributeMaxDynamicSharedMemorySize, FA_SMEM_D);

    // trig table + input conversions
    trig_kernel<<<(S*32)/256, 256>>>(trig);
    const int TOT4 = 1048576*3 + 262144*2;
    split_all_kernel<<<(TOT4/4 + 255)/256, 256>>>(hidden, Wq, Wk, Wv, Wo,
                                                  hHf, hLf, WqF, WkF, WvF, WoF);

    // QKV projections with fused rope + splits (no fp32 round-trip)
    qkv_gemm2<<<dim3(24, 16), 256, SM_TOTAL2>>>(hHf, hLf, WqF, WkF, WvF, trig,
                                                Qh, Ql, bKh, bKl, nKh, nKl, Vh, Vl);

    // single flash launch: 4 dual-split CTAs + 31 main tiles
    flash_all<<<dim3(DSPLIT + S/64 - 1, NH), 128, FA_SMEM_D>>>(
        Qh, Ql, bKh, bKl, nKh, nKl, Vh, Vl, aHf, aLf, pO, pm, pl);
    dual_merge<<<(64*NH*32 + 255)/256, 256>>>(pO, pm, pl, aHf, aLf);

    // 2-pass fp16 Wo GEMM into d_out
    wo_gemm2<<<dim3(16, 16), 256, SM_TOTAL2>>>(aHf, aLf, WoF, out);
}

// round 17
// speedup vs baseline: 1.1471x; 1.1471x over previous
#include <cuda_runtime.h>
#include <cuda_bf16.h>
#include <cuda_fp16.h>
#include <cstdint>

#define S     2048
#define HID   2048
#define NH    32
#define NKV   8
#define HD    64
#define KVDIM (NKV*HD)   // 512
#define CTX   (S-10)     // 2038: rows >= CTX use narrow rope

typedef unsigned long long ull;
typedef __nv_bfloat16 bf16;

__device__ __forceinline__ uint32_t smem_u32(const void* p) {
    uint32_t a;
    asm("{ .reg .u64 t; cvta.to.shared.u64 t, %1; cvt.u32.u64 %0, t; }" : "=r"(a) : "l"(p));
    return a;
}

// ---------------- mma.sync primitives (compute_103-safe) ----------------
__device__ __forceinline__ void cp16(uint32_t s, const void* g) {
    asm volatile("cp.async.cg.shared.global [%0], [%1], 16;" :: "r"(s), "l"(g));
}
#define CP_COMMIT() asm volatile("cp.async.commit_group;" ::: "memory")
#define CP_WAIT1()  asm volatile("cp.async.wait_group 1;" ::: "memory")

__device__ __forceinline__ void ldsm_x4(uint32_t addr, uint32_t& r0, uint32_t& r1,
                                        uint32_t& r2, uint32_t& r3) {
    asm volatile("ldmatrix.sync.aligned.m8n8.x4.shared.b16 {%0,%1,%2,%3}, [%4];"
                 : "=r"(r0), "=r"(r1), "=r"(r2), "=r"(r3) : "r"(addr));
}
__device__ __forceinline__ void ldsm_x4t(uint32_t addr, uint32_t& r0, uint32_t& r1,
                                         uint32_t& r2, uint32_t& r3) {
    asm volatile("ldmatrix.sync.aligned.m8n8.x4.trans.shared.b16 {%0,%1,%2,%3}, [%4];"
                 : "=r"(r0), "=r"(r1), "=r"(r2), "=r"(r3) : "r"(addr));
}
__device__ __forceinline__ void mma16816(float* c, const uint32_t* a, const uint32_t* b) {
    asm volatile(
        "mma.sync.aligned.m16n8k16.row.col.f32.bf16.bf16.f32 "
        "{%0,%1,%2,%3}, {%4,%5,%6,%7}, {%8,%9}, {%0,%1,%2,%3};"
        : "+f"(c[0]), "+f"(c[1]), "+f"(c[2]), "+f"(c[3])
        : "r"(a[0]), "r"(a[1]), "r"(a[2]), "r"(a[3]), "r"(b[0]), "r"(b[1]));
}
__device__ __forceinline__ void mma16816h(float* c, const uint32_t* a, const uint32_t* b) {
    asm volatile(
        "mma.sync.aligned.m16n8k16.row.col.f32.f16.f16.f32 "
        "{%0,%1,%2,%3}, {%4,%5,%6,%7}, {%8,%9}, {%0,%1,%2,%3};"
        : "+f"(c[0]), "+f"(c[1]), "+f"(c[2]), "+f"(c[3])
        : "r"(a[0]), "r"(a[1]), "r"(a[2]), "r"(a[3]), "r"(b[0]), "r"(b[1]));
}
__device__ __forceinline__ uint32_t pack_f16x2(float lo, float hi) {
    uint32_t r; asm("cvt.rn.f16x2.f32 %0, %1, %2;" : "=r"(r) : "f"(hi), "f"(lo));
    return r;
}

// ---------------- scratch (static device globals; no allocs) ----------------
__device__ float g_Q   [S*HID];
__device__ float g_K   [S*KVDIM];
__device__ float g_V   [S*KVDIM];
__device__ __half g_hHf[S*HID],   g_hLf[S*HID];    // hidden fp16 hi/lo
__device__ __half g_WqF[HID*HID];
__device__ __half g_WkF[KVDIM*HID];
__device__ __half g_WvF[KVDIM*HID];
__device__ __half g_WoF[HID*HID];
__device__ __half g_aHf[S*HID],  g_aLf[S*HID];     // attn out fp16 hi/lo
__device__ bf16 g_Qh[S*HID],    g_Ql[S*HID];
__device__ bf16 g_bKh[S*KVDIM], g_bKl[S*KVDIM];
__device__ bf16 g_nKh[S*KVDIM], g_nKl[S*KVDIM];
__device__ __half g_Vh[S*KVDIM], g_Vl[S*KVDIM];
__device__ float4 g_trig[S*32];                    // {cos_b, sin_b, cos_n, sin_n}
// dual split-K partials
#define DSPLIT 4
#define DTILES (32/DSPLIT)
__device__ float g_pO[DSPLIT*NH*64*64];
__device__ float g_pm[DSPLIT*NH*64];
__device__ float g_pl[DSPLIT*NH*64];

// ---------------- trig table (DP transcendentals computed once) ------------
__global__ __launch_bounds__(256)
void trig_kernel(float4* __restrict__ tab)
{
    int idx = blockIdx.x * 256 + threadIdx.x;   // 65536
    int s = idx >> 5, d = idx & 31;
    double inv = pow(10000.0, -(double)d / 32.0);
    double ab = (double)s * inv;
    double an = ((double)s * 0.25) * inv;
    tab[idx] = make_float4((float)cos(ab), (float)sin(ab),
                           (float)cos(an), (float)sin(an));
}

// ---------------- input conversions (one launch) ----------------------------
__global__ __launch_bounds__(256)
void split_all_kernel(const float* __restrict__ hid, const float* __restrict__ Wq,
                      const float* __restrict__ Wk,  const float* __restrict__ Wv,
                      const float* __restrict__ Wo,
                      __half* __restrict__ hH, __half* __restrict__ hL,
                      __half* __restrict__ qF, __half* __restrict__ kF,
                      __half* __restrict__ vF, __half* __restrict__ oF)
{
    int g0 = (blockIdx.x * 256 + threadIdx.x) * 4;
    const int R0 = 1048576, R1 = R0 + 1048576, R2 = R1 + 262144, R3 = R2 + 262144;
    const int TOT = R3 + 1048576;
    if (g0 >= TOT) return;
    if (g0 < R0) {
#pragma unroll
        for (int k = 0; k < 4; k++) {
            int i = g0 + k;
            float4 v = ((const float4*)hid)[i];
            __half h0 = __float2half_rn(v.x), h1 = __float2half_rn(v.y);
            __half h2 = __float2half_rn(v.z), h3 = __float2half_rn(v.w);
            ((__half2*)hH)[i*2+0] = __half2(h0, h1);
            ((__half2*)hH)[i*2+1] = __half2(h2, h3);
            ((__half2*)hL)[i*2+0] = __half2(__float2half_rn(v.x - __half2float(h0)),
                                            __float2half_rn(v.y - __half2float(h1)));
            ((__half2*)hL)[i*2+1] = __half2(__float2half_rn(v.z - __half2float(h2)),
                                            __float2half_rn(v.w - __half2float(h3)));
        }
        return;
    }
    const float* src; __half* dst; int rb;
    if (g0 < R1)      { src = Wq; dst = qF; rb = R0; }
    else if (g0 < R2) { src = Wk; dst = kF; rb = R1; }
    else if (g0 < R3) { src = Wv; dst = vF; rb = R2; }
    else              { src = Wo; dst = oF; rb = R3; }
#pragma unroll
    for (int k = 0; k < 4; k++) {
        int i = g0 - rb + k;
        float4 v = ((const float4*)src)[i];
        ((__half2*)dst)[i*2+0] = __half2(__float2half_rn(v.x), __float2half_rn(v.y));
        ((__half2*)dst)[i*2+1] = __half2(__float2half_rn(v.z), __float2half_rn(v.w));
    }
}

// ---------------- 2-pass fp16 GEMM core: C = (Ah+Al) @ Bh^T ----------------
#define STG2      16384
#define SM_STAGE2 (3*STG2)        // 48 KB
#define SM_TOTAL2 (2*SM_STAGE2)   // 96 KB -> 2 CTAs/SM

__device__ __forceinline__ void g_load_stage2(
    uint32_t sbuf,
    const __half* __restrict__ Ah, const __half* __restrict__ Al,
    const __half* __restrict__ Bh,
    int mBase, int nBase, int Kdim, int k0, int tid)
{
#pragma unroll
    for (int i = 0; i < 4; i++) {
        int u = i * 256 + tid;
        int r = u >> 3, c = u & 7;
        uint32_t so = (uint32_t)(r * 128 + ((c ^ (r & 7)) << 4));
        size_t eoffA = (size_t)(mBase + r) * Kdim + k0 + c * 8;
        size_t eoffB = (size_t)(nBase + r) * Kdim + k0 + c * 8;
        cp16(sbuf +          so, Ah + eoffA);
        cp16(sbuf +   STG2 + so, Al + eoffA);
        cp16(sbuf + 2*STG2 + so, Bh + eoffB);
    }
}

__device__ __forceinline__ void gemm2_body(
    const __half* __restrict__ Ah, const __half* __restrict__ Al,
    const __half* __restrict__ Bh, float* __restrict__ C,
    int Ntot, int Kdim, int mBase, int nBase, uint32_t sb)
{
    const int tid  = threadIdx.x;
    const int lane = tid & 31;
    const int wid  = tid >> 5;
    const int wm   = wid & 1;
    const int wn   = wid >> 1;

    float acc[4][4][4];
#pragma unroll
    for (int i = 0; i < 4; i++)
#pragma unroll
        for (int j = 0; j < 4; j++)
#pragma unroll
            for (int k = 0; k < 4; k++) acc[i][j][k] = 0.0f;

    const int NC = Kdim >> 6;

    g_load_stage2(sb,             Ah, Al, Bh, mBase, nBase, Kdim, 0,  tid);
    CP_COMMIT();
    g_load_stage2(sb + SM_STAGE2, Ah, Al, Bh, mBase, nBase, Kdim, 64, tid);
    CP_COMMIT();

    const int aRow = wm * 64;
    const int bRow = wn * 32;

    for (int c = 0; c < NC; c++) {
        CP_WAIT1();
        __syncthreads();
        const uint32_t sbuf = sb + (c & 1) * SM_STAGE2;
        const uint32_t sAh = sbuf, sAl = sbuf + STG2, sBh = sbuf + 2*STG2;

#pragma unroll
        for (int ks = 0; ks < 4; ks++) {
            uint32_t aH[4][4], aL[4][4], bH[4][2];
            {
                int rA = aRow + (lane & 15);
                int ccA = ks * 2 + (lane >> 4);
#pragma unroll
                for (int mf = 0; mf < 4; mf++) {
                    int r = rA + mf * 16;
                    uint32_t so = (uint32_t)(r * 128 + ((ccA ^ (r & 7)) << 4));
                    ldsm_x4(sAh + so, aH[mf][0], aH[mf][1], aH[mf][2], aH[mf][3]);
                    ldsm_x4(sAl + so, aL[mf][0], aL[mf][1], aL[mf][2], aL[mf][3]);
                }
            }
            {
                int rB0 = bRow + (lane & 7) + ((lane >> 4) << 3);
                int ccB = ks * 2 + ((lane >> 3) & 1);
#pragma unroll
                for (int nf2 = 0; nf2 < 2; nf2++) {
                    int r = rB0 + nf2 * 16;
                    uint32_t so = (uint32_t)(r * 128 + ((ccB ^ (r & 7)) << 4));
                    ldsm_x4(sBh + so, bH[nf2*2][0], bH[nf2*2][1], bH[nf2*2+1][0], bH[nf2*2+1][1]);
                }
            }
#pragma unroll
            for (int mf = 0; mf < 4; mf++)
#pragma unroll
                for (int nf = 0; nf < 4; nf++) {
                    mma16816h(acc[mf][nf], aH[mf], bH[nf]);
                    mma16816h(acc[mf][nf], aL[mf], bH[nf]);
                }
        }
        __syncthreads();
        if (c + 2 < NC)
            g_load_stage2(sb + (c & 1) * SM_STAGE2, Ah, Al, Bh,
                          mBase, nBase, Kdim, (c + 2) * 64, tid);
        CP_COMMIT();
    }

#pragma unroll
    for (int mf = 0; mf < 4; mf++) {
        int row0 = mBase + wm * 64 + mf * 16 + (lane >> 2);
#pragma unroll
        for (int nf = 0; nf < 4; nf++) {
            int col = nBase + wn * 32 + nf * 8 + (lane & 3) * 2;
            *(float2*)&C[(size_t)row0 * Ntot + col]       = make_float2(acc[mf][nf][0], acc[mf][nf][1]);
            *(float2*)&C[(size_t)(row0 + 8) * Ntot + col] = make_float2(acc[mf][nf][2], acc[mf][nf][3]);
        }
    }
}

__global__ __launch_bounds__(256, 2)
void qkv_gemm2(const __half* __restrict__ Ah, const __half* __restrict__ Al,
               const __half* __restrict__ WqF, const __half* __restrict__ WkF,
               const __half* __restrict__ WvF,
               float* __restrict__ Cq, float* __restrict__ Ck, float* __restrict__ Cv)
{
    extern __shared__ char dyns[];
    uint32_t sb = smem_u32(dyns);
    int bx = blockIdx.x, mBase = blockIdx.y * 128;
    if (bx < 16)      gemm2_body(Ah, Al, WqF, Cq, HID,   HID, mBase, bx*128,      sb);
    else if (bx < 20) gemm2_body(Ah, Al, WkF, Ck, KVDIM, HID, mBase, (bx-16)*128, sb);
    else              gemm2_body(Ah, Al, WvF, Cv, KVDIM, HID, mBase, (bx-20)*128, sb);
}

__global__ __launch_bounds__(256, 2)
void wo_gemm2(const __half* __restrict__ Ah, const __half* __restrict__ Al,
              const __half* __restrict__ Bh, float* __restrict__ C)
{
    extern __shared__ char dyns[];
    uint32_t sb = smem_u32(dyns);
    gemm2_body(Ah, Al, Bh, C, HID, HID, blockIdx.y*128, blockIdx.x*128, sb);
}

// ---------------- RoPE + split (float4-vectorized; trig from table) --------
__device__ __forceinline__ void split_w2(bf16* hp, bf16* lp, float x0, float x1) {
    bf16 h0 = __float2bfloat16(x0);
    bf16 h1 = __float2bfloat16(x1);
    *(__nv_bfloat162*)hp = __nv_bfloat162(h0, h1);
    *(__nv_bfloat162*)lp = __nv_bfloat162(__float2bfloat16(x0 - __bfloat162float(h0)),
                                          __float2bfloat16(x1 - __bfloat162float(h1)));
}

__global__ void rope_split_kernel(const float* __restrict__ Q, const float* __restrict__ K,
                                  const float* __restrict__ V,
                                  const float4* __restrict__ trig,
                                  bf16* __restrict__ qh, bf16* __restrict__ ql,
                                  bf16* __restrict__ kbh, bf16* __restrict__ kbl,
                                  bf16* __restrict__ knh, bf16* __restrict__ knl,
                                  __half* __restrict__ vh, __half* __restrict__ vl)
{
    const int s = blockIdx.x;
    const int tid = threadIdx.x; // 256
    const bool narrowRow = (s >= CTX);
    const float QS = 1.4426950408889634f * 0.125f;   // log2(e)/sqrt(64)

    __shared__ float cb[32], sb[32], cn[32], sn[32];
    if (tid < 32) {
        float4 t = trig[(size_t)s * 32 + tid];
        cb[tid] = t.x; sb[tid] = t.y; cn[tid] = t.z; sn[tid] = t.w;
    }
    __syncthreads();

    {
        int p = tid;
        int h = p >> 3, d4 = (p & 7) * 4;
        size_t base = (size_t)s * HID + h * HD;
        float4 x1 = *(const float4*)&Q[base + d4];
        float4 x2 = *(const float4*)&Q[base + d4 + 32];
        const float* cc = narrowRow ? cn : cb;
        const float* ss = narrowRow ? sn : sb;
        float c0 = cc[d4], c1 = cc[d4+1], c2 = cc[d4+2], c3 = cc[d4+3];
        float s0 = ss[d4], s1 = ss[d4+1], s2 = ss[d4+2], s3 = ss[d4+3];
        split_w2(qh + base + d4,     ql + base + d4,
                 (x1.x*c0 - x2.x*s0)*QS, (x1.y*c1 - x2.y*s1)*QS);
        split_w2(qh + base + d4 + 2, ql + base + d4 + 2,
                 (x1.z*c2 - x2.z*s2)*QS, (x1.w*c3 - x2.w*s3)*QS);
        split_w2(qh + base + d4 + 32, ql + base + d4 + 32,
                 (x2.x*c0 + x1.x*s0)*QS, (x2.y*c1 + x1.y*s1)*QS);
        split_w2(qh + base + d4 + 34, ql + base + d4 + 34,
                 (x2.z*c2 + x1.z*s2)*QS, (x2.w*c3 + x1.w*s3)*QS);
    }
    if (tid < NKV * 8) {
        int p = tid;
        int h = p >> 3, d4 = (p & 7) * 4;
        size_t base = (size_t)s * KVDIM + h * HD;
        float4 x1 = *(const float4*)&K[base + d4];
        float4 x2 = *(const float4*)&K[base + d4 + 32];
        float cb0 = cb[d4], cb1 = cb[d4+1], cb2 = cb[d4+2], cb3 = cb[d4+3];
        float sb0 = sb[d4], sb1 = sb[d4+1], sb2 = sb[d4+2], sb3 = sb[d4+3];
        float cn0 = cn[d4], cn1 = cn[d4+1], cn2 = cn[d4+2], cn3 = cn[d4+3];
        float sn0 = sn[d4], sn1 = sn[d4+1], sn2 = sn[d4+2], sn3 = sn[d4+3];
        split_w2(kbh + base + d4,     kbl + base + d4,
                 x1.x*cb0 - x2.x*sb0, x1.y*cb1 - x2.y*sb1);
        split_w2(kbh + base + d4 + 2, kbl + base + d4 + 2,
                 x1.z*cb2 - x2.z*sb2, x1.w*cb3 - x2.w*sb3);
        split_w2(kbh + base + d4 + 32, kbl + base + d4 + 32,
                 x2.x*cb0 + x1.x*sb0, x2.y*cb1 + x1.y*sb1);
        split_w2(kbh + base + d4 + 34, kbl + base + d4 + 34,
                 x2.z*cb2 + x1.z*sb2, x2.w*cb3 + x1.w*sb3);
        split_w2(knh + base + d4,     knl + base + d4,
                 x1.x*cn0 - x2.x*sn0, x1.y*cn1 - x2.y*sn1);
        split_w2(knh + base + d4 + 2, knl + base + d4 + 2,
                 x1.z*cn2 - x2.z*sn2, x1.w*cn3 - x2.w*sn3);
        split_w2(knh + base + d4 + 32, knl + base + d4 + 32,
                 x2.x*cn0 + x1.x*sn0, x2.y*cn1 + x1.y*sn1);
        split_w2(knh + base + d4 + 34, knl + base + d4 + 34,
                 x2.z*cn2 + x1.z*sn2, x2.w*cn3 + x1.w*sn3);
    }
    if (tid < KVDIM / 4) {
        size_t base = (size_t)s * KVDIM + tid * 4;
        float4 v = *(const float4*)&V[base];
        __half h0 = __float2half_rn(v.x), h1 = __float2half_rn(v.y);
        __half h2 = __float2half_rn(v.z), h3 = __float2half_rn(v.w);
        *(__half2*)(vh + base)     = __half2(h0, h1);
        *(__half2*)(vh + base + 2) = __half2(h2, h3);
        *(__half2*)(vl + base)     = __half2(__float2half_rn(v.x - __half2float(h0)),
                                             __float2half_rn(v.y - __half2float(h1)));
        *(__half2*)(vl + base + 2) = __half2(__float2half_rn(v.z - __half2float(h2)),
                                             __float2half_rn(v.w - __half2float(h3)));
    }
}

// ---------------- Tensor-core flash attention (R15-exact) ------------------
template<bool DUAL>
__device__ __forceinline__ void fa_load_stage(
    uint32_t sb, int kt, int kvh, int tid,
    const bf16* __restrict__ Kbh, const bf16* __restrict__ Kbl,
    const bf16* __restrict__ Knh, const bf16* __restrict__ Knl,
    const __half* __restrict__ Vh, const __half* __restrict__ Vl)
{
#pragma unroll
    for (int i = 0; i < 4; i++) {
        int u = i * 128 + tid;
        int r = u >> 3, c = u & 7;
        uint32_t so = (uint32_t)(r * 128 + ((c ^ (r & 7)) << 4));
        size_t go = (size_t)(kt * 64 + r) * KVDIM + kvh * 64 + c * 8;
        cp16(sb +         so, Kbh + go);
        cp16(sb + 8192  + so, Kbl + go);
        cp16(sb + 16384 + so, Vh + go);
        cp16(sb + 24576 + so, Vl + go);
        if (DUAL) {
            cp16(sb + 32768 + so, Knh + go);
            cp16(sb + 40960 + so, Knl + go);
        }
    }
}

__device__ __forceinline__ void fa_compute_S(
    float s[8][4], uint32_t sKh, uint32_t sKl,
    const uint32_t qfh[4][4], const uint32_t qfl[4][4], int lane)
{
#pragma unroll
    for (int kk = 0; kk < 4; kk++) {
        uint32_t kh[8][2], kl[8][2];
        int rB0 = (lane & 7) + ((lane >> 4) << 3);
        int ccB = kk * 2 + ((lane >> 3) & 1);
#pragma unroll
        for (int nb = 0; nb < 4; nb++) {
            int r = nb * 16 + rB0;
            uint32_t so = (uint32_t)(r * 128 + ((ccB ^ (r & 7)) << 4));
            ldsm_x4(sKh + so, kh[nb*2][0], kh[nb*2][1], kh[nb*2+1][0], kh[nb*2+1][1]);
            ldsm_x4(sKl + so, kl[nb*2][0], kl[nb*2][1], kl[nb*2+1][0], kl[nb*2+1][1]);
        }
#pragma unroll
        for (int nf = 0; nf < 8; nf++) {
            mma16816(s[nf], qfh[kk], kh[nf]);
            mma16816(s[nf], qfl[kk], kh[nf]);
            mma16816(s[nf], qfh[kk], kl[nf]);
        }
    }
}

__device__ __forceinline__ void fa_load_qfrag(
    uint32_t sQ, const bf16* __restrict__ Qh, const bf16* __restrict__ Ql,
    int qt, int h, int tid)
{
    const bf16* gQh = Qh + (size_t)(qt * 64) * HID + h * 64;
    const bf16* gQl = Ql + (size_t)(qt * 64) * HID + h * 64;
#pragma unroll
    for (int i = 0; i < 4; i++) {
        int u = i * 128 + tid;
        int r = u >> 3, c = u & 7;
        uint32_t so = (uint32_t)(r * 128 + ((c ^ (r & 7)) << 4));
        cp16(sQ +        so, gQh + (size_t)r * HID + c * 8);
        cp16(sQ + 8192 + so, gQl + (size_t)r * HID + c * 8);
    }
}

struct FaState {
    float o[8][4];
    float m0, m1, l0, l1;
};

__device__ __forceinline__ void fa_softmax_pv(
    FaState& st, float s[8][4], uint32_t sb, int lane)
{
    float mr0 = -1e30f, mr1 = -1e30f;
#pragma unroll
    for (int nf = 0; nf < 8; nf++) {
        mr0 = fmaxf(mr0, fmaxf(s[nf][0], s[nf][1]));
        mr1 = fmaxf(mr1, fmaxf(s[nf][2], s[nf][3]));
    }
    mr0 = fmaxf(mr0, __shfl_xor_sync(0xffffffffu, mr0, 1));
    mr0 = fmaxf(mr0, __shfl_xor_sync(0xffffffffu, mr0, 2));
    mr1 = fmaxf(mr1, __shfl_xor_sync(0xffffffffu, mr1, 1));
    mr1 = fmaxf(mr1, __shfl_xor_sync(0xffffffffu, mr1, 2));

    float mn0 = fmaxf(st.m0, mr0), mn1 = fmaxf(st.m1, mr1);
    float sc0 = exp2f(st.m0 - mn0), sc1 = exp2f(st.m1 - mn1);
    st.m0 = mn0; st.m1 = mn1;
    st.l0 *= sc0; st.l1 *= sc1;
#pragma unroll
    for (int nf = 0; nf < 8; nf++) {
        st.o[nf][0] *= sc0; st.o[nf][1] *= sc0;
        st.o[nf][2] *= sc1; st.o[nf][3] *= sc1;
    }

    uint32_t pF[4][4];
    float sum0 = 0.0f, sum1 = 0.0f;
#pragma unroll
    for (int nf = 0; nf < 8; nf++) {
        float p0 = exp2f(s[nf][0] - st.m0), p1 = exp2f(s[nf][1] - st.m0);
        float p2 = exp2f(s[nf][2] - st.m1), p3 = exp2f(s[nf][3] - st.m1);
        sum0 += p0 + p1; sum1 += p2 + p3;
        int kk = nf >> 1;
        int off = (nf & 1) * 2;
        pF[kk][off + 0] = pack_f16x2(p0, p1);
        pF[kk][off + 1] = pack_f16x2(p2, p3);
    }
    sum0 += __shfl_xor_sync(0xffffffffu, sum0, 1);
    sum0 += __shfl_xor_sync(0xffffffffu, sum0, 2);
    sum1 += __shfl_xor_sync(0xffffffffu, sum1, 1);
    sum1 += __shfl_xor_sync(0xffffffffu, sum1, 2);
    st.l0 += sum0; st.l1 += sum1;

    const uint32_t sVh = sb + 16384, sVl = sb + 24576;
#pragma unroll
    for (int kk = 0; kk < 4; kk++) {
        uint32_t vh[8][2], vl[8][2];
        int key0 = kk * 16 + (lane & 7) + ((lane >> 3) & 1) * 8;
#pragma unroll
        for (int nb = 0; nb < 4; nb++) {
            int chunk = nb * 2 + (lane >> 4);
            uint32_t so = (uint32_t)(key0 * 128 + ((chunk ^ (key0 & 7)) << 4));
            ldsm_x4t(sVh + so, vh[nb*2][0], vh[nb*2][1], vh[nb*2+1][0], vh[nb*2+1][1]);
            ldsm_x4t(sVl + so, vl[nb*2][0], vl[nb*2][1], vl[nb*2+1][0], vl[nb*2+1][1]);
        }
#pragma unroll
        for (int nf = 0; nf < 8; nf++) {
            mma16816h(st.o[nf], pF[kk], vh[nf]);
            mma16816h(st.o[nf], pF[kk], vl[nf]);
        }
    }
}

__global__ __launch_bounds__(128, 2)
void flash_all(const bf16* __restrict__ Qh, const bf16* __restrict__ Ql,
               const bf16* __restrict__ Kbh, const bf16* __restrict__ Kbl,
               const bf16* __restrict__ Knh, const bf16* __restrict__ Knl,
               const __half* __restrict__ Vh,  const __half* __restrict__ Vl,
               __half* __restrict__ aHf, __half* __restrict__ aLf,
               float* __restrict__ pO, float* __restrict__ pm,
               float* __restrict__ pl)
{
    extern __shared__ char dyn[];
    const uint32_t sQ = smem_u32(dyn);
    const int tid = threadIdx.x, lane = tid & 31, w = tid >> 5;
    const int h = blockIdx.y, kvh = h >> 2;
    const bool isDual = (blockIdx.x < DSPLIT);

    FaState st;
#pragma unroll
    for (int nf = 0; nf < 8; nf++)
#pragma unroll
        for (int j = 0; j < 4; j++) st.o[nf][j] = 0.0f;
    st.m0 = -1e30f; st.m1 = -1e30f; st.l0 = 0.0f; st.l1 = 0.0f;

    if (isDual) {
        constexpr int STAGE = 49152;
        const int split = blockIdx.x;
        const int qt = S/64 - 1;
        const int kt0 = split * DTILES, kt1 = kt0 + DTILES;

        fa_load_qfrag(sQ, Qh, Ql, qt, h, tid);
        fa_load_stage<true>(sQ + 16384, kt0, kvh, tid, Kbh, Kbl, Knh, Knl, Vh, Vl);
        CP_COMMIT();
        fa_load_stage<true>(sQ + 16384 + STAGE, kt0 + 1, kvh, tid, Kbh, Kbl, Knh, Knl, Vh, Vl);
        CP_COMMIT();
        CP_WAIT1();
        __syncthreads();

        uint32_t qfh[4][4], qfl[4][4];
        {
            int rA = w * 16 + (lane & 15);
#pragma unroll
            for (int kk = 0; kk < 4; kk++) {
                int cc = kk * 2 + (lane >> 4);
                uint32_t so = (uint32_t)(rA * 128 + ((cc ^ (rA & 7)) << 4));
                ldsm_x4(sQ + so,        qfh[kk][0], qfh[kk][1], qfh[kk][2], qfh[kk][3]);
                ldsm_x4(sQ + 8192 + so, qfl[kk][0], qfl[kk][1], qfl[kk][2], qfl[kk][3]);
            }
        }

        const int rl0 = w * 16 + (lane >> 2);
        const int rl1 = rl0 + 8;
        const int rg0 = qt * 64 + rl0, rg1 = qt * 64 + rl1;

        for (int kt = kt0; kt < kt1; kt++) {
            if (kt > kt0) { CP_WAIT1(); __syncthreads(); }
            const uint32_t sb = sQ + 16384 + (kt & 1) * STAGE;

            float s[8][4];
#pragma unroll
            for (int nf = 0; nf < 8; nf++)
#pragma unroll
                for (int j = 0; j < 4; j++) s[nf][j] = 0.0f;
            fa_compute_S(s, sb, sb + 8192, qfh, qfl, lane);

            {
                float sn[8][4];
#pragma unroll
                for (int nf = 0; nf < 8; nf++)
#pragma unroll
                    for (int j = 0; j < 4; j++) sn[nf][j] = 0.0f;
                fa_compute_S(sn, sb + 32768, sb + 40960, qfh, qfl, lane);
                if (rg0 >= CTX) {
#pragma unroll
                    for (int nf = 0; nf < 8; nf++) { s[nf][0] = sn[nf][0]; s[nf][1] = sn[nf][1]; }
                }
                if (rg1 >= CTX) {
#pragma unroll
                    for (int nf = 0; nf < 8; nf++) { s[nf][2] = sn[nf][2]; s[nf][3] = sn[nf][3]; }
                }
            }

            if (kt == qt) {
#pragma unroll
                for (int nf = 0; nf < 8; nf++) {
                    int c0 = kt * 64 + nf * 8 + (lane & 3) * 2;
                    if (c0     > rg0) s[nf][0] = -1e30f;
                    if (c0 + 1 > rg0) s[nf][1] = -1e30f;
                    if (c0     > rg1) s[nf][2] = -1e30f;
                    if (c0 + 1 > rg1) s[nf][3] = -1e30f;
                }
            }

            fa_softmax_pv(st, s, sb, lane);

            __syncthreads();
            if (kt + 2 < kt1)
                fa_load_stage<true>(sQ + 16384 + (kt & 1) * STAGE, kt + 2, kvh, tid,
                                    Kbh, Kbl, Knh, Knl, Vh, Vl);
            CP_COMMIT();
        }

        const int hb = (split * NH + h) * 64;
#pragma unroll
        for (int nf = 0; nf < 8; nf++) {
            int col = nf * 8 + (lane & 3) * 2;
            *(float2*)&pO[(size_t)(hb + rl0) * 64 + col] = make_float2(st.o[nf][0], st.o[nf][1]);
            *(float2*)&pO[(size_t)(hb + rl1) * 64 + col] = make_float2(st.o[nf][2], st.o[nf][3]);
        }
        if ((lane & 3) == 0) {
            pm[hb + rl0] = st.m0; pl[hb + rl0] = st.l0;
            pm[hb + rl1] = st.m1; pl[hb + rl1] = st.l1;
        }
        return;
    }

    {
        constexpr int STAGE = 32768;
        const int qt = (S/64 - 2) - ((int)blockIdx.x - DSPLIT);

        fa_load_qfrag(sQ, Qh, Ql, qt, h, tid);
        fa_load_stage<false>(sQ + 16384, 0, kvh, tid, Kbh, Kbl, nullptr, nullptr, Vh, Vl);
        CP_COMMIT();
        if (qt >= 1)
            fa_load_stage<false>(sQ + 16384 + STAGE, 1, kvh, tid, Kbh, Kbl, nullptr, nullptr, Vh, Vl);
        CP_COMMIT();
        CP_WAIT1();
        __syncthreads();

        uint32_t qfh[4][4], qfl[4][4];
        {
            int rA = w * 16 + (lane & 15);
#pragma unroll
            for (int kk = 0; kk < 4; kk++) {
                int cc = kk * 2 + (lane >> 4);
                uint32_t so = (uint32_t)(rA * 128 + ((cc ^ (rA & 7)) << 4));
                ldsm_x4(sQ + so,        qfh[kk][0], qfh[kk][1], qfh[kk][2], qfh[kk][3]);
                ldsm_x4(sQ + 8192 + so, qfl[kk][0], qfl[kk][1], qfl[kk][2], qfl[kk][3]);
            }
        }

        const int rg0 = qt * 64 + w * 16 + (lane >> 2);
        const int rg1 = rg0 + 8;

        for (int kt = 0; kt <= qt; kt++) {
            if (kt) { CP_WAIT1(); __syncthreads(); }
            const uint32_t sb = sQ + 16384 + (kt & 1) * STAGE;

            float s[8][4];
#pragma unroll
            for (int nf = 0; nf < 8; nf++)
#pragma unroll
                for (int j = 0; j < 4; j++) s[nf][j] = 0.0f;
            fa_compute_S(s, sb, sb + 8192, qfh, qfl, lane);

            if (kt == qt) {
#pragma unroll
                for (int nf = 0; nf < 8; nf++) {
                    int c0 = kt * 64 + nf * 8 + (lane & 3) * 2;
                    if (c0     > rg0) s[nf][0] = -1e30f;
                    if (c0 + 1 > rg0) s[nf][1] = -1e30f;
                    if (c0     > rg1) s[nf][2] = -1e30f;
                    if (c0 + 1 > rg1) s[nf][3] = -1e30f;
                }
            }

            fa_softmax_pv(st, s, sb, lane);

            __syncthreads();
            if (kt + 2 <= qt)
                fa_load_stage<false>(sQ + 16384 + (kt & 1) * STAGE, kt + 2, kvh, tid,
                                     Kbh, Kbl, nullptr, nullptr, Vh, Vl);
            CP_COMMIT();
        }

        float inv0 = 1.0f / st.l0, inv1 = 1.0f / st.l1;
#pragma unroll
        for (int nf = 0; nf < 8; nf++) {
            int col = h * 64 + nf * 8 + (lane & 3) * 2;
            float x0 = st.o[nf][0]*inv0, x1 = st.o[nf][1]*inv0;
            float x2 = st.o[nf][2]*inv1, x3 = st.o[nf][3]*inv1;
            float r0 = __half2float(__float2half_rn(x0));
            float r1 = __half2float(__float2half_rn(x1));
            float r2 = __half2float(__float2half_rn(x2));
            float r3 = __half2float(__float2half_rn(x3));
            *(uint32_t*)&aHf[(size_t)rg0 * HID + col] = pack_f16x2(x0, x1);
            *(uint32_t*)&aLf[(size_t)rg0 * HID + col] = pack_f16x2(x0 - r0, x1 - r1);
            *(uint32_t*)&aHf[(size_t)rg1 * HID + col] = pack_f16x2(x2, x3);
            *(uint32_t*)&aLf[(size_t)rg1 * HID + col] = pack_f16x2(x2 - r2, x3 - r3);
        }
    }
}

// ---- merge dual partials -> fp16 hi/lo attn output (exact reassociation) --
__global__ __launch_bounds__(256)
void dual_merge(const float* __restrict__ pO, const float* __restrict__ pm,
                const float* __restrict__ pl,
                __half* __restrict__ aHf, __half* __restrict__ aLf)
{
    int idx = blockIdx.x * 256 + threadIdx.x;
    if (idx >= 64 * NH * 32) return;
    int dp = idx & 31;
    int h  = (idx >> 5) & 31;
    int rl = idx >> 10;

    float m[DSPLIT], l[DSPLIT];
#pragma unroll
    for (int i = 0; i < DSPLIT; i++) {
        m[i] = pm[(i * NH + h) * 64 + rl];
        l[i] = pl[(i * NH + h) * 64 + rl];
    }
    float M = m[0];
#pragma unroll
    for (int i = 1; i < DSPLIT; i++) M = fmaxf(M, m[i]);
    float wgt[DSPLIT], L = 0.0f;
#pragma unroll
    for (int i = 0; i < DSPLIT; i++) { wgt[i] = exp2f(m[i] - M); L += l[i] * wgt[i]; }

    float o0 = 0.0f, o1 = 0.0f;
#pragma unroll
    for (int i = 0; i < DSPLIT; i++) {
        float2 v = *(const float2*)&pO[(size_t)((i * NH + h) * 64 + rl) * 64 + dp * 2];
        o0 += v.x * wgt[i];
        o1 += v.y * wgt[i];
    }
    float inv = 1.0f / L;
    o0 *= inv; o1 *= inv;

    size_t off = (size_t)((S - 64) + rl) * HID + h * 64 + dp * 2;
    float r0 = __half2float(__float2half_rn(o0));
    float r1 = __half2float(__float2half_rn(o1));
    *(uint32_t*)&aHf[off] = pack_f16x2(o0, o1);
    *(uint32_t*)&aLf[off] = pack_f16x2(o0 - r0, o1 - r1);
}

// ---------------- launch ----------------
extern "C" void kernel_launch(void* const* d_in, const int* in_sizes, int n_in,
                              void* d_out, int out_size)
{
    const float* hidden = (const float*)d_in[0];
    const float* Wq = (const float*)d_in[3];
    const float* Wk = (const float*)d_in[4];
    const float* Wv = (const float*)d_in[5];
    const float* Wo = (const float*)d_in[6];
    float* out = (float*)d_out;

    float *qB, *kB, *vB;
    cudaGetSymbolAddress((void**)&qB,  g_Q);
    cudaGetSymbolAddress((void**)&kB,  g_K);
    cudaGetSymbolAddress((void**)&vB,  g_V);

    __half *hHf,*hLf,*WqF,*WkF,*WvF,*WoF,*aHf,*aLf;
    cudaGetSymbolAddress((void**)&hHf, g_hHf); cudaGetSymbolAddress((void**)&hLf, g_hLf);
    cudaGetSymbolAddress((void**)&WqF, g_WqF); cudaGetSymbolAddress((void**)&WkF, g_WkF);
    cudaGetSymbolAddress((void**)&WvF, g_WvF); cudaGetSymbolAddress((void**)&WoF, g_WoF);
    cudaGetSymbolAddress((void**)&aHf, g_aHf); cudaGetSymbolAddress((void**)&aLf, g_aLf);

    bf16 *Qh,*Ql,*bKh,*bKl,*nKh,*nKl;
    __half *Vh,*Vl;
    cudaGetSymbolAddress((void**)&Qh,  g_Qh);  cudaGetSymbolAddress((void**)&Ql,  g_Ql);
    cudaGetSymbolAddress((void**)&bKh, g_bKh); cudaGetSymbolAddress((void**)&bKl, g_bKl);
    cudaGetSymbolAddress((void**)&nKh, g_nKh); cudaGetSymbolAddress((void**)&nKl, g_nKl);
    cudaGetSymbolAddress((void**)&Vh,  g_Vh);  cudaGetSymbolAddress((void**)&Vl,  g_Vl);

    float4* trig;
    cudaGetSymbolAddress((void**)&trig, g_trig);

    float *pO, *pm, *pl;
    cudaGetSymbolAddress((void**)&pO, g_pO);
    cudaGetSymbolAddress((void**)&pm, g_pm);
    cudaGetSymbolAddress((void**)&pl, g_pl);

    cudaFuncSetAttribute(qkv_gemm2, cudaFuncAttributeMaxDynamicSharedMemorySize, SM_TOTAL2);
    cudaFuncSetAttribute(wo_gemm2,  cudaFuncAttributeMaxDynamicSharedMemorySize, SM_TOTAL2);
    const int FA_SMEM_D = 16384 + 2*49152;   // 114688
    cudaFuncSetAttribute(flash_all, cudaFuncAttributeMaxDynamicSharedMemorySize, FA_SMEM_D);

    // trig table (once) + input conversions
    trig_kernel<<<(S*32)/256, 256>>>(trig);
    const int TOT4 = 1048576*3 + 262144*2;
    split_all_kernel<<<(TOT4/4 + 255)/256, 256>>>(hidden, Wq, Wk, Wv, Wo,
                                                  hHf, hLf, WqF, WkF, WvF, WoF);

    // QKV projections: 2-pass fp16, 2 CTAs/SM (R15-exact)
    qkv_gemm2<<<dim3(24, 16), 256, SM_TOTAL2>>>(hHf, hLf, WqF, WkF, WvF, qB, kB, vB);

    // rope + splits (trig from table; no DP in hot kernel)
    rope_split_kernel<<<S, 256>>>(qB, kB, vB, trig, Qh, Ql, bKh, bKl, nKh, nKl, Vh, Vl);

    // single flash launch: 4 dual-split CTAs + 31 main tiles
    flash_all<<<dim3(DSPLIT + S/64 - 1, NH), 128, FA_SMEM_D>>>(
        Qh, Ql, bKh, bKl, nKh, nKl, Vh, Vl, aHf, aLf, pO, pm, pl);
    dual_merge<<<(64*NH*32 + 255)/256, 256>>>(pO, pm, pl, aHf, aLf);

    // 2-pass fp16 Wo GEMM into d_out
    wo_gemm2<<<dim3(16, 16), 256, SM_TOTAL2>>>(aHf, aLf, WoF, out);
}